// round 1
// baseline (speedup 1.0000x reference)
#include <cuda_runtime.h>
#include <cuda_fp16.h>

#define M_TOTAL 4096
#define N_TOTAL 11008
#define K_TOTAL 4096
#define PACKN   (N_TOTAL * (K_TOTAL / 2))   // packed int count = 22,544,384

// Scratch: fp16 copies of x and unpacked integer weights (exact in fp16).
__device__ __align__(16) __half g_x[(size_t)M_TOTAL * K_TOTAL];           // 33.5 MB
__device__ __align__(16) __half g_w[(size_t)N_TOTAL * K_TOTAL];           // 90.2 MB

// ---------------------------------------------------------------------------
// Pre-pass 1: x fp32 -> fp16 (8 floats / thread)
// ---------------------------------------------------------------------------
__global__ void convert_x_kernel(const float* __restrict__ x) {
    int i = blockIdx.x * blockDim.x + threadIdx.x;   // i indexes 8-float chunks
    const float4* xv = (const float4*)x;
    float4 a = xv[2 * i];
    float4 b = xv[2 * i + 1];
    __half2 h0 = __floats2half2_rn(a.x, a.y);
    __half2 h1 = __floats2half2_rn(a.z, a.w);
    __half2 h2 = __floats2half2_rn(b.x, b.y);
    __half2 h3 = __floats2half2_rn(b.z, b.w);
    uint4 u;
    u.x = *(const unsigned int*)&h0;
    u.y = *(const unsigned int*)&h1;
    u.z = *(const unsigned int*)&h2;
    u.w = *(const unsigned int*)&h3;
    ((uint4*)g_x)[i] = u;
}

// ---------------------------------------------------------------------------
// Pre-pass 2: unpack int4 nibbles -> fp16 integers (exact). Scale applied in
// the GEMM epilogue instead, so the GEMM operands are exact.
// lo nibble -> even k, hi nibble -> odd k (matches reference stack/reshape).
// ---------------------------------------------------------------------------
__device__ __forceinline__ __half2 unpack_pair(int v) {
    int lo = (v & 15) - 8;
    int hi = ((v >> 4) & 15) - 8;
    return __halves2half2(__int2half_rn(lo), __int2half_rn(hi));
}

__global__ void convert_w_kernel(const int* __restrict__ wp) {
    int i = blockIdx.x * blockDim.x + threadIdx.x;   // i indexes 4-int chunks
    int4 p = ((const int4*)wp)[i];
    __half2 h0 = unpack_pair(p.x);
    __half2 h1 = unpack_pair(p.y);
    __half2 h2 = unpack_pair(p.z);
    __half2 h3 = unpack_pair(p.w);
    uint4 u;
    u.x = *(const unsigned int*)&h0;
    u.y = *(const unsigned int*)&h1;
    u.z = *(const unsigned int*)&h2;
    u.w = *(const unsigned int*)&h3;
    ((uint4*)g_w)[i] = u;
}

// ---------------------------------------------------------------------------
// GEMM: C[M,N] = Xh[M,K] * Wh[N,K]^T, fp16 inputs, fp32 accumulate.
// Epilogue: out = acc * scale[n] + bias[n].
// Block tile 128x128x32, 8 warps (2x4), warp tile 64x32, mma m16n8k16.
// Double-buffered cp.async pipeline.
// ---------------------------------------------------------------------------
#define BM 128
#define BN 128
#define BK 32
#define KT (K_TOTAL / BK)       // 128 iterations
#define AST 40                  // smem row stride (halves): 32 + 8 pad
#define BST 40

__device__ __forceinline__ void cp_async16(void* smem, const void* gmem) {
    unsigned int s = (unsigned int)__cvta_generic_to_shared(smem);
    asm volatile("cp.async.cg.shared.global [%0], [%1], 16;\n" :: "r"(s), "l"(gmem));
}

__global__ __launch_bounds__(256, 2)
void gemm_f16_kernel(const float* __restrict__ scale,
                     const float* __restrict__ bias,
                     float* __restrict__ out) {
    __shared__ __half As[2][BM * AST];
    __shared__ __half Bs[2][BN * BST];

    const int tid  = threadIdx.x;
    const int lane = tid & 31;
    const int warp = tid >> 5;
    const int wm   = (warp >> 2) * 64;   // warp M offset within block tile
    const int wn   = (warp & 3) * 32;    // warp N offset within block tile
    const int m0   = blockIdx.y * BM;
    const int n0   = blockIdx.x * BN;

    float acc[4][4][4];
    #pragma unroll
    for (int i = 0; i < 4; i++)
        #pragma unroll
        for (int j = 0; j < 4; j++)
            #pragma unroll
            for (int r = 0; r < 4; r++) acc[i][j][r] = 0.0f;

    // --- tile loader: 512 16B-chunks per operand, 2 per thread each ---
    auto load_tiles = [&](int buf, int kbase) {
        #pragma unroll
        for (int j = 0; j < 2; j++) {
            int c   = tid + j * 256;
            int row = c >> 2;
            int ko  = (c & 3) * 8;
            cp_async16(&As[buf][row * AST + ko],
                       &g_x[(size_t)(m0 + row) * K_TOTAL + kbase + ko]);
            cp_async16(&Bs[buf][row * BST + ko],
                       &g_w[(size_t)(n0 + row) * K_TOTAL + kbase + ko]);
        }
        asm volatile("cp.async.commit_group;\n");
    };

    load_tiles(0, 0);

    for (int kt = 0; kt < KT; kt++) {
        const int buf = kt & 1;
        asm volatile("cp.async.wait_group 0;\n");
        __syncthreads();                 // buf ready for all; buf^1 free (computed last iter)
        if (kt + 1 < KT) load_tiles(buf ^ 1, (kt + 1) * BK);

        const __half* A = As[buf];
        const __half* B = Bs[buf];

        #pragma unroll
        for (int ks = 0; ks < 2; ks++) {
            unsigned int a[4][4], b[4][2];
            // A fragments: ldmatrix x4 per 16-row m-tile
            #pragma unroll
            for (int mt = 0; mt < 4; mt++) {
                int r  = wm + mt * 16 + (lane & 15);
                int kk = ks * 16 + ((lane >> 4) << 3);
                unsigned int addr =
                    (unsigned int)__cvta_generic_to_shared(&A[r * AST + kk]);
                asm volatile(
                    "ldmatrix.sync.aligned.m8n8.x4.shared.b16 {%0,%1,%2,%3}, [%4];"
                    : "=r"(a[mt][0]), "=r"(a[mt][1]), "=r"(a[mt][2]), "=r"(a[mt][3])
                    : "r"(addr));
            }
            // B fragments: ldmatrix x2 per 8-col n-tile (k-major rows -> col-major frag)
            #pragma unroll
            for (int nt = 0; nt < 4; nt++) {
                int r  = wn + nt * 8 + (lane & 7);
                int kk = ks * 16 + (((lane >> 3) & 1) << 3);
                unsigned int addr =
                    (unsigned int)__cvta_generic_to_shared(&B[r * BST + kk]);
                asm volatile(
                    "ldmatrix.sync.aligned.m8n8.x2.shared.b16 {%0,%1}, [%2];"
                    : "=r"(b[nt][0]), "=r"(b[nt][1])
                    : "r"(addr));
            }
            #pragma unroll
            for (int mt = 0; mt < 4; mt++) {
                #pragma unroll
                for (int nt = 0; nt < 4; nt++) {
                    asm volatile(
                        "mma.sync.aligned.m16n8k16.row.col.f32.f16.f16.f32 "
                        "{%0,%1,%2,%3}, {%4,%5,%6,%7}, {%8,%9}, {%0,%1,%2,%3};"
                        : "+f"(acc[mt][nt][0]), "+f"(acc[mt][nt][1]),
                          "+f"(acc[mt][nt][2]), "+f"(acc[mt][nt][3])
                        : "r"(a[mt][0]), "r"(a[mt][1]), "r"(a[mt][2]), "r"(a[mt][3]),
                          "r"(b[nt][0]), "r"(b[nt][1]));
                }
            }
        }
        __syncthreads();                 // done reading buf before it is refilled
    }

    // --- epilogue: out = acc * scale[n] + bias[n] ---
    const int g = lane >> 2;
    const int t = lane & 3;
    #pragma unroll
    for (int nt = 0; nt < 4; nt++) {
        const int col = n0 + wn + nt * 8 + t * 2;
        const float s0 = __ldg(&scale[col]);
        const float s1 = __ldg(&scale[col + 1]);
        const float b0 = __ldg(&bias[col]);
        const float b1 = __ldg(&bias[col + 1]);
        #pragma unroll
        for (int mt = 0; mt < 4; mt++) {
            const int row0 = m0 + wm + mt * 16 + g;
            float2 v0, v1;
            v0.x = acc[mt][nt][0] * s0 + b0;
            v0.y = acc[mt][nt][1] * s1 + b1;
            v1.x = acc[mt][nt][2] * s0 + b0;
            v1.y = acc[mt][nt][3] * s1 + b1;
            *(float2*)&out[(size_t)row0 * N_TOTAL + col] = v0;
            *(float2*)&out[(size_t)(row0 + 8) * N_TOTAL + col] = v1;
        }
    }
}

// ---------------------------------------------------------------------------
extern "C" void kernel_launch(void* const* d_in, const int* in_sizes, int n_in,
                              void* d_out, int out_size) {
    const float* x     = (const float*)d_in[0];
    const int*   wp    = (const int*)d_in[1];
    const float* scale = (const float*)d_in[2];
    const float* bias  = (const float*)d_in[3];
    float*       out   = (float*)d_out;

    // x: 16,777,216 floats / 8 per thread = 2,097,152 threads
    convert_x_kernel<<<8192, 256>>>(x);
    // w: 22,544,384 ints / 4 per thread = 5,636,096 threads
    convert_w_kernel<<<22016, 256>>>(wp);
    // GEMM: grid (N/128, M/128) = (86, 32)
    gemm_f16_kernel<<<dim3(86, 32), 256>>>(scale, bias, out);
}

// round 3
// speedup vs baseline: 1.2167x; 1.2167x over previous
#include <cuda_runtime.h>
#include <cuda_fp16.h>

#define M_TOTAL 4096
#define N_TOTAL 11008
#define K_TOTAL 4096

// Scratch: fp16 copies of x and unpacked integer weights (exact in fp16).
__device__ __align__(16) __half g_x[(size_t)M_TOTAL * K_TOTAL];   // 33.5 MB
__device__ __align__(16) __half g_w[(size_t)N_TOTAL * K_TOTAL];   // 90.2 MB

// ---------------------------------------------------------------------------
// Pre-pass 1: x fp32 -> fp16 (8 floats / thread)
// ---------------------------------------------------------------------------
__global__ void convert_x_kernel(const float* __restrict__ x) {
    int i = blockIdx.x * blockDim.x + threadIdx.x;
    const float4* xv = (const float4*)x;
    float4 a = xv[2 * i];
    float4 b = xv[2 * i + 1];
    __half2 h0 = __floats2half2_rn(a.x, a.y);
    __half2 h1 = __floats2half2_rn(a.z, a.w);
    __half2 h2 = __floats2half2_rn(b.x, b.y);
    __half2 h3 = __floats2half2_rn(b.z, b.w);
    uint4 u;
    u.x = *(const unsigned int*)&h0;
    u.y = *(const unsigned int*)&h1;
    u.z = *(const unsigned int*)&h2;
    u.w = *(const unsigned int*)&h3;
    ((uint4*)g_x)[i] = u;
}

// ---------------------------------------------------------------------------
// Pre-pass 2: unpack int4 nibbles -> fp16 integers (exact; scale in epilogue)
// ---------------------------------------------------------------------------
__device__ __forceinline__ __half2 unpack_pair(int v) {
    int lo = (v & 15) - 8;
    int hi = ((v >> 4) & 15) - 8;
    return __halves2half2(__int2half_rn(lo), __int2half_rn(hi));
}

__global__ void convert_w_kernel(const int* __restrict__ wp) {
    int i = blockIdx.x * blockDim.x + threadIdx.x;
    int4 p = ((const int4*)wp)[i];
    __half2 h0 = unpack_pair(p.x);
    __half2 h1 = unpack_pair(p.y);
    __half2 h2 = unpack_pair(p.z);
    __half2 h3 = unpack_pair(p.w);
    uint4 u;
    u.x = *(const unsigned int*)&h0;
    u.y = *(const unsigned int*)&h1;
    u.z = *(const unsigned int*)&h2;
    u.w = *(const unsigned int*)&h3;
    ((uint4*)g_w)[i] = u;
}

// ---------------------------------------------------------------------------
// GEMM: C[M,N] = Xh[M,K] * Wh[N,K]^T, fp16 in, fp32 acc, mma.sync m16n8k16.
// 128x128x32 block tile, 4-stage cp.async pipeline, register-double-buffered
// fragments, one __syncthreads per k-step, GM=8 supertile swizzle for L2.
// ---------------------------------------------------------------------------
#define BM 128
#define BN 128
#define BK 32
#define STAGES 4
#define KT (K_TOTAL / BK)          // 128
#define AST 40                     // padded row stride in halves
#define ASTAGE (BM * AST)          // halves per A stage (5120)
#define BSTAGE (BN * AST)

__device__ __forceinline__ void cp_async16(void* smem_p, const void* gmem) {
    unsigned int s = (unsigned int)__cvta_generic_to_shared(smem_p);
    asm volatile("cp.async.cg.shared.global [%0], [%1], 16;\n" :: "r"(s), "l"(gmem));
}

__device__ __forceinline__ void frag_a_load(unsigned int a[4][4],
                                            const __half* A, int wm,
                                            int lane, int ks) {
    #pragma unroll
    for (int mt = 0; mt < 4; mt++) {
        int r  = wm + mt * 16 + (lane & 15);
        int kk = ks * 16 + ((lane >> 4) << 3);
        unsigned int addr = (unsigned int)__cvta_generic_to_shared(&A[r * AST + kk]);
        asm volatile("ldmatrix.sync.aligned.m8n8.x4.shared.b16 {%0,%1,%2,%3}, [%4];"
                     : "=r"(a[mt][0]), "=r"(a[mt][1]), "=r"(a[mt][2]), "=r"(a[mt][3])
                     : "r"(addr));
    }
}

__device__ __forceinline__ void frag_b_load(unsigned int b[4][2],
                                            const __half* B, int wn,
                                            int lane, int ks) {
    #pragma unroll
    for (int nt = 0; nt < 4; nt++) {
        int r  = wn + nt * 8 + (lane & 7);
        int kk = ks * 16 + (((lane >> 3) & 1) << 3);
        unsigned int addr = (unsigned int)__cvta_generic_to_shared(&B[r * AST + kk]);
        asm volatile("ldmatrix.sync.aligned.m8n8.x2.shared.b16 {%0,%1}, [%2];"
                     : "=r"(b[nt][0]), "=r"(b[nt][1])
                     : "r"(addr));
    }
}

__device__ __forceinline__ void mma_tile(float acc[4][4][4],
                                         const unsigned int a[4][4],
                                         const unsigned int b[4][2]) {
    #pragma unroll
    for (int mt = 0; mt < 4; mt++) {
        #pragma unroll
        for (int nt = 0; nt < 4; nt++) {
            asm volatile(
                "mma.sync.aligned.m16n8k16.row.col.f32.f16.f16.f32 "
                "{%0,%1,%2,%3}, {%4,%5,%6,%7}, {%8,%9}, {%0,%1,%2,%3};"
                : "+f"(acc[mt][nt][0]), "+f"(acc[mt][nt][1]),
                  "+f"(acc[mt][nt][2]), "+f"(acc[mt][nt][3])
                : "r"(a[mt][0]), "r"(a[mt][1]), "r"(a[mt][2]), "r"(a[mt][3]),
                  "r"(b[nt][0]), "r"(b[nt][1]));
        }
    }
}

__global__ __launch_bounds__(256, 1)
void gemm_f16_kernel(const float* __restrict__ scale,
                     const float* __restrict__ bias,
                     float* __restrict__ out) {
    extern __shared__ __half smem[];
    __half* As = smem;                       // STAGES * ASTAGE halves
    __half* Bs = smem + STAGES * ASTAGE;     // STAGES * BSTAGE halves

    const int tid  = threadIdx.x;
    const int lane = tid & 31;
    const int warp = tid >> 5;
    const int wm   = (warp >> 2) * 64;
    const int wn   = (warp & 3) * 32;

    // Supertile swizzle: 8 consecutive CTAs share one N-tile (B reuse in L2);
    // a 148-CTA wave spans only ~19 N-columns.
    const int PN = N_TOTAL / BN;             // 86
    const int GM = 8;                        // M_TOTAL/BM = 32, divisible
    int pid   = blockIdx.x;
    int group = pid / (GM * PN);
    int rem   = pid % (GM * PN);
    const int m0 = (group * GM + (rem % GM)) * BM;
    const int n0 = (rem / GM) * BN;

    float acc[4][4][4];
    #pragma unroll
    for (int i = 0; i < 4; i++)
        #pragma unroll
        for (int j = 0; j < 4; j++)
            #pragma unroll
            for (int r = 0; r < 4; r++) acc[i][j][r] = 0.0f;

    // Tile loader: 512 16B-chunks per operand per stage, 2 per thread each.
    auto load_tiles = [&](int buf, int kbase) {
        #pragma unroll
        for (int j = 0; j < 2; j++) {
            int c   = tid + j * 256;
            int row = c >> 2;
            int ko  = (c & 3) * 8;
            cp_async16(&As[buf * ASTAGE + row * AST + ko],
                       &g_x[(size_t)(m0 + row) * K_TOTAL + kbase + ko]);
            cp_async16(&Bs[buf * BSTAGE + row * AST + ko],
                       &g_w[(size_t)(n0 + row) * K_TOTAL + kbase + ko]);
        }
    };

    // Prologue: fill STAGES-1 stages.
    #pragma unroll
    for (int s = 0; s < STAGES - 1; s++) {
        load_tiles(s, s * BK);
        asm volatile("cp.async.commit_group;\n");
    }
    asm volatile("cp.async.wait_group %0;\n" :: "n"(STAGES - 2));
    __syncthreads();

    unsigned int a0[4][4], b0[4][2], a1[4][4], b1[4][2];
    int rs = 0;
    frag_a_load(a0, &As[0], wm, lane, 0);
    frag_b_load(b0, &Bs[0], wn, lane, 0);

    #pragma unroll 4
    for (int kt = 0; kt < KT; kt++) {
        // -- half 1: prefetch ks=1 frags, issue gmem loads for stage kt+3 --
        frag_a_load(a1, &As[rs * ASTAGE], wm, lane, 1);
        frag_b_load(b1, &Bs[rs * BSTAGE], wn, lane, 1);
        if (kt + STAGES - 1 < KT) {
            load_tiles((rs + STAGES - 1) & (STAGES - 1), (kt + STAGES - 1) * BK);
        }
        asm volatile("cp.async.commit_group;\n");   // unconditional: keeps accounting
        mma_tile(acc, a0, b0);

        // -- half 2: next stage resident, prefetch its ks=0 frags --
        asm volatile("cp.async.wait_group %0;\n" :: "n"(STAGES - 2));
        __syncthreads();
        rs = (rs + 1) & (STAGES - 1);
        frag_a_load(a0, &As[rs * ASTAGE], wm, lane, 0);   // harmless garbage on last iter
        frag_b_load(b0, &Bs[rs * BSTAGE], wn, lane, 0);
        mma_tile(acc, a1, b1);
    }

    // --- epilogue: out = acc * scale[n] + bias[n] ---
    const int g = lane >> 2;
    const int t = lane & 3;
    #pragma unroll
    for (int nt = 0; nt < 4; nt++) {
        const int col = n0 + wn + nt * 8 + t * 2;
        const float s0 = __ldg(&scale[col]);
        const float s1 = __ldg(&scale[col + 1]);
        const float bb0 = __ldg(&bias[col]);
        const float bb1 = __ldg(&bias[col + 1]);
        #pragma unroll
        for (int mt = 0; mt < 4; mt++) {
            const int row0 = m0 + wm + mt * 16 + g;
            float2 v0, v1;
            v0.x = acc[mt][nt][0] * s0 + bb0;
            v0.y = acc[mt][nt][1] * s1 + bb1;
            v1.x = acc[mt][nt][2] * s0 + bb0;
            v1.y = acc[mt][nt][3] * s1 + bb1;
            *(float2*)&out[(size_t)row0 * N_TOTAL + col] = v0;
            *(float2*)&out[(size_t)(row0 + 8) * N_TOTAL + col] = v1;
        }
    }
}

// ---------------------------------------------------------------------------
extern "C" void kernel_launch(void* const* d_in, const int* in_sizes, int n_in,
                              void* d_out, int out_size) {
    const float* x     = (const float*)d_in[0];
    const int*   wp    = (const int*)d_in[1];
    const float* scale = (const float*)d_in[2];
    const float* bias  = (const float*)d_in[3];
    float*       out   = (float*)d_out;

    convert_x_kernel<<<8192, 256>>>(x);
    convert_w_kernel<<<22016, 256>>>(wp);

    const int smem_bytes = STAGES * (ASTAGE + BSTAGE) * sizeof(__half);  // 81920
    cudaFuncSetAttribute(gemm_f16_kernel,
                         cudaFuncAttributeMaxDynamicSharedMemorySize, smem_bytes);
    const int grid = (M_TOTAL / BM) * (N_TOTAL / BN);   // 2752
    gemm_f16_kernel<<<grid, 256, smem_bytes>>>(scale, bias, out);
}

// round 4
// speedup vs baseline: 1.5373x; 1.2634x over previous
#include <cuda_runtime.h>
#include <cuda_fp16.h>

#define M_TOTAL 4096
#define N_TOTAL 11008
#define K_TOTAL 4096

// Scratch: fp16 copies of x and unpacked integer weights (exact in fp16).
__device__ __align__(16) __half g_x[(size_t)M_TOTAL * K_TOTAL];   // 33.5 MB
__device__ __align__(16) __half g_w[(size_t)N_TOTAL * K_TOTAL];   // 90.2 MB

// ---------------------------------------------------------------------------
// Pre-pass 1: x fp32 -> fp16 (8 floats / thread)
// ---------------------------------------------------------------------------
__global__ void convert_x_kernel(const float* __restrict__ x) {
    int i = blockIdx.x * blockDim.x + threadIdx.x;
    const float4* xv = (const float4*)x;
    float4 a = xv[2 * i];
    float4 b = xv[2 * i + 1];
    __half2 h0 = __floats2half2_rn(a.x, a.y);
    __half2 h1 = __floats2half2_rn(a.z, a.w);
    __half2 h2 = __floats2half2_rn(b.x, b.y);
    __half2 h3 = __floats2half2_rn(b.z, b.w);
    uint4 u;
    u.x = *(const unsigned int*)&h0;
    u.y = *(const unsigned int*)&h1;
    u.z = *(const unsigned int*)&h2;
    u.w = *(const unsigned int*)&h3;
    ((uint4*)g_x)[i] = u;
}

// ---------------------------------------------------------------------------
// Pre-pass 2: unpack int4 nibbles -> fp16 integers (exact; scale in epilogue)
// ---------------------------------------------------------------------------
__device__ __forceinline__ __half2 unpack_pair(int v) {
    int lo = (v & 15) - 8;
    int hi = ((v >> 4) & 15) - 8;
    return __halves2half2(__int2half_rn(lo), __int2half_rn(hi));
}

__global__ void convert_w_kernel(const int* __restrict__ wp) {
    int i = blockIdx.x * blockDim.x + threadIdx.x;
    int4 p = ((const int4*)wp)[i];
    __half2 h0 = unpack_pair(p.x);
    __half2 h1 = unpack_pair(p.y);
    __half2 h2 = unpack_pair(p.z);
    __half2 h3 = unpack_pair(p.w);
    uint4 u;
    u.x = *(const unsigned int*)&h0;
    u.y = *(const unsigned int*)&h1;
    u.z = *(const unsigned int*)&h2;
    u.w = *(const unsigned int*)&h3;
    ((uint4*)g_w)[i] = u;
}

// ---------------------------------------------------------------------------
// GEMM: C[M,N] = Xh[M,K] * Wh[N,K]^T, fp16 in, fp32 acc, mma.sync m16n8k16.
// Block tile 128x256x32, warp tile 64x64 (2x4 warps), 4-stage cp.async
// pipeline, register double-buffered fragments, GM=8 supertile swizzle.
// ---------------------------------------------------------------------------
#define BM 128
#define BN 256
#define BK 32
#define STAGES 4
#define KT (K_TOTAL / BK)          // 128
#define AST 40                     // padded row stride in halves (80B)
#define ASTAGE (BM * AST)          // 5120 halves
#define BSTAGE (BN * AST)          // 10240 halves

__device__ __forceinline__ void cp_async16(void* smem_p, const void* gmem) {
    unsigned int s = (unsigned int)__cvta_generic_to_shared(smem_p);
    asm volatile("cp.async.cg.shared.global [%0], [%1], 16;\n" :: "r"(s), "l"(gmem));
}

// A fragments: 4 m16 tiles, ldmatrix.x4 each.
__device__ __forceinline__ void frag_a_load(unsigned int a[4][4],
                                            const __half* A, int wm,
                                            int lane, int ks) {
    #pragma unroll
    for (int mt = 0; mt < 4; mt++) {
        int r  = wm + mt * 16 + (lane & 15);
        int kk = ks * 16 + ((lane >> 4) << 3);
        unsigned int addr = (unsigned int)__cvta_generic_to_shared(&A[r * AST + kk]);
        asm volatile("ldmatrix.sync.aligned.m8n8.x4.shared.b16 {%0,%1,%2,%3}, [%4];"
                     : "=r"(a[mt][0]), "=r"(a[mt][1]), "=r"(a[mt][2]), "=r"(a[mt][3])
                     : "r"(addr));
    }
}

// B fragments: 8 n8 tiles, one ldmatrix.x4 per PAIR of n8 tiles.
// x4 register order: [rows p..p+8, k lo], [rows p..p+8, k hi],
//                    [rows p+8..p+16, k lo], [rows p+8..p+16, k hi]
__device__ __forceinline__ void frag_b_load(unsigned int b[8][2],
                                            const __half* B, int wn,
                                            int lane, int ks) {
    #pragma unroll
    for (int np = 0; np < 4; np++) {
        int r  = wn + np * 16 + (((lane >> 4) & 1) << 3) + (lane & 7);
        int kk = ks * 16 + (((lane >> 3) & 1) << 3);
        unsigned int addr = (unsigned int)__cvta_generic_to_shared(&B[r * AST + kk]);
        asm volatile("ldmatrix.sync.aligned.m8n8.x4.shared.b16 {%0,%1,%2,%3}, [%4];"
                     : "=r"(b[2 * np][0]), "=r"(b[2 * np][1]),
                       "=r"(b[2 * np + 1][0]), "=r"(b[2 * np + 1][1])
                     : "r"(addr));
    }
}

__device__ __forceinline__ void mma_tile(float acc[4][8][4],
                                         const unsigned int a[4][4],
                                         const unsigned int b[8][2]) {
    #pragma unroll
    for (int mt = 0; mt < 4; mt++) {
        #pragma unroll
        for (int nt = 0; nt < 8; nt++) {
            asm volatile(
                "mma.sync.aligned.m16n8k16.row.col.f32.f16.f16.f32 "
                "{%0,%1,%2,%3}, {%4,%5,%6,%7}, {%8,%9}, {%0,%1,%2,%3};"
                : "+f"(acc[mt][nt][0]), "+f"(acc[mt][nt][1]),
                  "+f"(acc[mt][nt][2]), "+f"(acc[mt][nt][3])
                : "r"(a[mt][0]), "r"(a[mt][1]), "r"(a[mt][2]), "r"(a[mt][3]),
                  "r"(b[nt][0]), "r"(b[nt][1]));
        }
    }
}

__global__ __launch_bounds__(256, 1)
void gemm_f16_kernel(const float* __restrict__ scale,
                     const float* __restrict__ bias,
                     float* __restrict__ out) {
    extern __shared__ __half smem[];
    __half* As = smem;                       // STAGES * ASTAGE halves
    __half* Bs = smem + STAGES * ASTAGE;     // STAGES * BSTAGE halves

    const int tid  = threadIdx.x;
    const int lane = tid & 31;
    const int warp = tid >> 5;
    const int wm   = (warp >> 2) * 64;       // 2 warp rows
    const int wn   = (warp & 3) * 64;        // 4 warp cols

    // Supertile swizzle: 8 consecutive CTAs share one N-tile.
    const int PN = N_TOTAL / BN;             // 43
    const int GM = 8;                        // M_TOTAL/BM = 32, divisible
    int pid   = blockIdx.x;
    int group = pid / (GM * PN);
    int rem   = pid % (GM * PN);
    const int m0 = (group * GM + (rem % GM)) * BM;
    const int n0 = (rem / GM) * BN;

    float acc[4][8][4];
    #pragma unroll
    for (int i = 0; i < 4; i++)
        #pragma unroll
        for (int j = 0; j < 8; j++)
            #pragma unroll
            for (int r = 0; r < 4; r++) acc[i][j][r] = 0.0f;

    // Tile loader: A 512 + B 1024 16B-chunks per stage; 2 + 4 per thread.
    auto load_tiles = [&](int buf, int kbase) {
        #pragma unroll
        for (int j = 0; j < 2; j++) {
            int c   = tid + j * 256;
            int row = c >> 2;
            int ko  = (c & 3) * 8;
            cp_async16(&As[buf * ASTAGE + row * AST + ko],
                       &g_x[(size_t)(m0 + row) * K_TOTAL + kbase + ko]);
        }
        #pragma unroll
        for (int j = 0; j < 4; j++) {
            int c   = tid + j * 256;
            int row = c >> 2;
            int ko  = (c & 3) * 8;
            cp_async16(&Bs[buf * BSTAGE + row * AST + ko],
                       &g_w[(size_t)(n0 + row) * K_TOTAL + kbase + ko]);
        }
    };

    // Prologue: fill STAGES-1 stages.
    #pragma unroll
    for (int s = 0; s < STAGES - 1; s++) {
        load_tiles(s, s * BK);
        asm volatile("cp.async.commit_group;\n");
    }
    asm volatile("cp.async.wait_group %0;\n" :: "n"(STAGES - 2));
    __syncthreads();

    unsigned int a0[4][4], b0[8][2], a1[4][4], b1[8][2];
    int rs = 0;
    frag_a_load(a0, &As[0], wm, lane, 0);
    frag_b_load(b0, &Bs[0], wn, lane, 0);

    for (int kt = 0; kt < KT; kt++) {
        // -- half 1: prefetch ks=1 frags, issue gmem loads for stage kt+3 --
        frag_a_load(a1, &As[rs * ASTAGE], wm, lane, 1);
        frag_b_load(b1, &Bs[rs * BSTAGE], wn, lane, 1);
        if (kt + STAGES - 1 < KT) {
            load_tiles((rs + STAGES - 1) & (STAGES - 1), (kt + STAGES - 1) * BK);
        }
        asm volatile("cp.async.commit_group;\n");
        mma_tile(acc, a0, b0);

        // -- half 2: next stage resident, prefetch its ks=0 frags --
        asm volatile("cp.async.wait_group %0;\n" :: "n"(STAGES - 2));
        __syncthreads();
        rs = (rs + 1) & (STAGES - 1);
        frag_a_load(a0, &As[rs * ASTAGE], wm, lane, 0);   // garbage on last iter, unused
        frag_b_load(b0, &Bs[rs * BSTAGE], wn, lane, 0);
        mma_tile(acc, a1, b1);
    }

    // --- epilogue: out = acc * scale[n] + bias[n] ---
    const int g = lane >> 2;
    const int t = lane & 3;
    #pragma unroll
    for (int nt = 0; nt < 8; nt++) {
        const int col = n0 + wn + nt * 8 + t * 2;
        const float s0 = __ldg(&scale[col]);
        const float s1 = __ldg(&scale[col + 1]);
        const float bb0 = __ldg(&bias[col]);
        const float bb1 = __ldg(&bias[col + 1]);
        #pragma unroll
        for (int mt = 0; mt < 4; mt++) {
            const int row0 = m0 + wm + mt * 16 + g;
            float2 v0, v1;
            v0.x = acc[mt][nt][0] * s0 + bb0;
            v0.y = acc[mt][nt][1] * s1 + bb1;
            v1.x = acc[mt][nt][2] * s0 + bb0;
            v1.y = acc[mt][nt][3] * s1 + bb1;
            *(float2*)&out[(size_t)row0 * N_TOTAL + col] = v0;
            *(float2*)&out[(size_t)(row0 + 8) * N_TOTAL + col] = v1;
        }
    }
}

// ---------------------------------------------------------------------------
extern "C" void kernel_launch(void* const* d_in, const int* in_sizes, int n_in,
                              void* d_out, int out_size) {
    const float* x     = (const float*)d_in[0];
    const int*   wp    = (const int*)d_in[1];
    const float* scale = (const float*)d_in[2];
    const float* bias  = (const float*)d_in[3];
    float*       out   = (float*)d_out;

    convert_x_kernel<<<8192, 256>>>(x);
    convert_w_kernel<<<22016, 256>>>(wp);

    const int smem_bytes = STAGES * (ASTAGE + BSTAGE) * sizeof(__half);  // 122880
    cudaFuncSetAttribute(gemm_f16_kernel,
                         cudaFuncAttributeMaxDynamicSharedMemorySize, smem_bytes);
    const int grid = (M_TOTAL / BM) * (N_TOTAL / BN);   // 32 * 43 = 1376
    gemm_f16_kernel<<<grid, 256, smem_bytes>>>(scale, bias, out);
}